// round 1
// baseline (speedup 1.0000x reference)
#include <cuda_runtime.h>
#include <math.h>

#define D_MODEL 768
#define N_HEADS 12
#define HEAD_DIM 64
#define SEQ 2048
#define BATCH 2
#define QKV_N (3 * D_MODEL)
#define M_TOK (BATCH * SEQ)
#define SCALE 0.125f

// Scratch (allocation-free rule: __device__ globals)
__device__ float g_qkv[(size_t)M_TOK * QKV_N];    // [B*S, 3*D]  (Q | K | V), head-major within each D
__device__ float g_attn[(size_t)M_TOK * D_MODEL]; // [B*S, D] attention output

// ---------------------------------------------------------------------------
// Generic tiled SGEMM: C[M,N] = A[M,K] @ B[K,N] (+ bias[N] if non-null)
// BM=BN=64, BK=16, 256 threads, 4x4 micro-tile per thread.
// All problem dims here are exact multiples of the tile sizes.
// ---------------------------------------------------------------------------
__global__ __launch_bounds__(256) void gemm64(const float* __restrict__ A,
                                              const float* __restrict__ B,
                                              const float* __restrict__ bias,
                                              float* __restrict__ C,
                                              int M, int N, int K)
{
    __shared__ float As[16][65];   // [k][m], padded to kill STS conflicts
    __shared__ float Bs[16][64];   // [k][n]

    const int tid = threadIdx.x;
    const int tx  = tid & 15;      // 0..15 -> N
    const int ty  = tid >> 4;      // 0..15 -> M
    const int row0 = blockIdx.y * 64;
    const int col0 = blockIdx.x * 64;

    float acc[4][4] = {};

    for (int k0 = 0; k0 < K; k0 += 16) {
        // A tile: 64x16
        #pragma unroll
        for (int i = 0; i < 4; i++) {
            int idx = tid + i * 256;
            int r = idx >> 4, c = idx & 15;
            As[c][r] = A[(size_t)(row0 + r) * K + (k0 + c)];
        }
        // B tile: 16x64
        #pragma unroll
        for (int i = 0; i < 4; i++) {
            int idx = tid + i * 256;
            int r = idx >> 6, c = idx & 63;
            Bs[r][c] = B[(size_t)(k0 + r) * N + (col0 + c)];
        }
        __syncthreads();

        #pragma unroll
        for (int kk = 0; kk < 16; kk++) {
            float a[4], b[4];
            #pragma unroll
            for (int i = 0; i < 4; i++) a[i] = As[kk][ty * 4 + i];
            #pragma unroll
            for (int j = 0; j < 4; j++) b[j] = Bs[kk][tx * 4 + j];
            #pragma unroll
            for (int i = 0; i < 4; i++)
                #pragma unroll
                for (int j = 0; j < 4; j++)
                    acc[i][j] += a[i] * b[j];
        }
        __syncthreads();
    }

    #pragma unroll
    for (int i = 0; i < 4; i++) {
        int r = row0 + ty * 4 + i;
        #pragma unroll
        for (int j = 0; j < 4; j++) {
            int c = col0 + tx * 4 + j;
            float v = acc[i][j];
            if (bias) v += bias[c];
            C[(size_t)r * N + c] = v;
        }
    }
}

// ---------------------------------------------------------------------------
// Flash-style causal attention.
// Block = 64 query rows of one (b, h). 64 threads, 1 thread per query row.
// Q and the output accumulator live in registers (64+64 floats/thread).
// K/V tiles (64x64) in smem, read broadcast. Scores in smem, column-major
// (Ss[j*64 + tid]) so each thread owns a conflict-free column.
// Causal: only k-tiles kt <= qt are visited; diagonal tile masks j > tid.
// ---------------------------------------------------------------------------
__global__ __launch_bounds__(64) void flash64(const float* __restrict__ qkv,
                                              float* __restrict__ out)
{
    extern __shared__ float sm[];
    float* Ks = sm;                 // 64*64
    float* Vs = sm + 64 * 64;       // 64*64
    float* Ss = sm + 2 * 64 * 64;   // 64*64, column-major per thread

    const int tid = threadIdx.x;       // query row within tile
    const int qt  = blockIdx.x;        // q tile index
    const int h   = blockIdx.y;
    const int b   = blockIdx.z;
    const int q   = qt * 64 + tid;

    const float* qptr = qkv + ((size_t)(b * SEQ + q)) * QKV_N + h * HEAD_DIM;

    float qreg[HEAD_DIM];
    #pragma unroll
    for (int d = 0; d < HEAD_DIM; d++) qreg[d] = qptr[d];

    float acc[HEAD_DIM];
    #pragma unroll
    for (int d = 0; d < HEAD_DIM; d++) acc[d] = 0.f;

    float m = -INFINITY;
    float l = 0.f;

    for (int kt = 0; kt <= qt; kt++) {
        __syncthreads();  // previous Ks/Vs consumers done
        const float* kbase = qkv + ((size_t)(b * SEQ + kt * 64)) * QKV_N + D_MODEL + h * HEAD_DIM;
        const float* vbase = kbase + D_MODEL;
        for (int i = tid; i < 64 * 64; i += 64) {
            int r = i >> 6, c = i & 63;
            Ks[i] = kbase[(size_t)r * QKV_N + c];
            Vs[i] = vbase[(size_t)r * QKV_N + c];
        }
        __syncthreads();

        const int jmax = (kt == qt) ? (tid + 1) : 64;  // causal within diagonal tile

        // Pass 1: scores + tile max
        float tm = -INFINITY;
        for (int j = 0; j < jmax; j++) {
            float s = 0.f;
            #pragma unroll
            for (int d = 0; d < HEAD_DIM; d++) s += qreg[d] * Ks[j * 64 + d];
            s *= SCALE;
            Ss[j * 64 + tid] = s;
            tm = fmaxf(tm, s);
        }

        // Online softmax rescale
        float mn = fmaxf(m, tm);
        float alpha = __expf(m - mn);   // exp(-inf) = 0 on first tile
        l *= alpha;
        #pragma unroll
        for (int d = 0; d < HEAD_DIM; d++) acc[d] *= alpha;

        // Pass 2: accumulate P @ V
        for (int j = 0; j < jmax; j++) {
            float p = __expf(Ss[j * 64 + tid] - mn);
            l += p;
            const float* vrow = Vs + j * 64;
            #pragma unroll
            for (int d = 0; d < HEAD_DIM; d++) acc[d] += p * vrow[d];
        }
        m = mn;
    }

    const float inv = 1.f / l;
    float* optr = out + ((size_t)(b * SEQ + q)) * D_MODEL + h * HEAD_DIM;
    #pragma unroll
    for (int d = 0; d < HEAD_DIM; d++) optr[d] = acc[d] * inv;
}

// ---------------------------------------------------------------------------
// Launch: QKV GEMM -> flash attention -> output projection (+bias)
// Inputs (metadata order): x, attn_mask(bool, ignored: causal is known),
//                          W_qkv, W_proj, b_proj
// ---------------------------------------------------------------------------
extern "C" void kernel_launch(void* const* d_in, const int* in_sizes, int n_in,
                              void* d_out, int out_size)
{
    (void)in_sizes; (void)n_in; (void)out_size;
    const float* x      = (const float*)d_in[0];
    const float* W_qkv  = (const float*)d_in[2];
    const float* W_proj = (const float*)d_in[3];
    const float* b_proj = (const float*)d_in[4];
    float* out = (float*)d_out;

    float *qkv, *attn;
    cudaGetSymbolAddress((void**)&qkv,  g_qkv);
    cudaGetSymbolAddress((void**)&attn, g_attn);

    const int flash_smem = 3 * 64 * 64 * (int)sizeof(float);  // 48 KB
    cudaFuncSetAttribute(flash64, cudaFuncAttributeMaxDynamicSharedMemorySize, flash_smem);

    // 1) QKV projection: [4096,768] @ [768,2304]
    gemm64<<<dim3(QKV_N / 64, M_TOK / 64), 256>>>(x, W_qkv, nullptr, qkv,
                                                  M_TOK, QKV_N, D_MODEL);

    // 2) causal flash attention per (q-tile, head, batch)
    flash64<<<dim3(SEQ / 64, N_HEADS, BATCH), 64, flash_smem>>>(qkv, attn);

    // 3) output projection + bias: [4096,768] @ [768,768]
    gemm64<<<dim3(D_MODEL / 64, M_TOK / 64), 256>>>(attn, W_proj, b_proj, out,
                                                    M_TOK, D_MODEL, D_MODEL);
}